// round 2
// baseline (speedup 1.0000x reference)
#include <cuda_runtime.h>
#include <cstdint>

// Problem constants
#define C_IN   256
#define C_OUT  256
#define Hh     64
#define Ww     256
#define PIX    (Hh*Ww)          // 16384 pixels per (i,b)
#define HOUT   (12*Hh)          // 768

// Tiling
#define KB        32            // K chunk
#define ROWPAD    132           // 128 + 4 floats: conflict-free fragment LDS
#define STAGE_F   (KB*ROWPAD)   // floats per tile per stage
#define SMEM_BYTES (2 /*stages*/ * 2 /*tiles*/ * STAGE_F * 4)

struct XPtrs { const float* p[12]; };

__device__ __forceinline__ uint32_t f2tf32(float v) {
    uint32_t r;
    asm("cvt.rna.tf32.f32 %0, %1;" : "=r"(r) : "f"(v));
    return r;
}

__device__ __forceinline__ void mma_tf32(float& d0, float& d1, float& d2, float& d3,
                                         uint32_t a0, uint32_t a1, uint32_t a2, uint32_t a3,
                                         uint32_t b0, uint32_t b1) {
    asm volatile(
        "mma.sync.aligned.m16n8k8.row.col.f32.tf32.tf32.f32 "
        "{%0,%1,%2,%3},{%4,%5,%6,%7},{%8,%9},{%0,%1,%2,%3};"
        : "+f"(d0), "+f"(d1), "+f"(d2), "+f"(d3)
        : "r"(a0), "r"(a1), "r"(a2), "r"(a3), "r"(b0), "r"(b1));
}

__device__ __forceinline__ void cp16_cg(float* s, const float* g) {
    uint32_t sa = (uint32_t)__cvta_generic_to_shared(s);
    asm volatile("cp.async.cg.shared.global [%0], [%1], 16;\n" :: "r"(sa), "l"(g));
}
__device__ __forceinline__ void cp16_ca(float* s, const float* g) {
    uint32_t sa = (uint32_t)__cvta_generic_to_shared(s);
    asm volatile("cp.async.ca.shared.global [%0], [%1], 16;\n" :: "r"(sa), "l"(g));
}

// D[o,p] = sum_c W[c,o] * X[c,p]   (A = W tile K-major natural, B = X tile natural)
// out[bb, o, 12h+i, w] = D + b[o]*count(12h+i)
__global__ void __launch_bounds__(256, 2)
conv_interleave_kernel(XPtrs xs, const float* __restrict__ Wg,
                       const float* __restrict__ bg, float* __restrict__ out)
{
    extern __shared__ float smem[];

    const int tid  = threadIdx.x;
    const int lane = tid & 31;
    const int warp = tid >> 5;
    const int gid  = lane >> 2;   // groupID
    const int tig  = lane & 3;    // thread-in-group

    const int p0 = blockIdx.x * 128;        // pixel tile base (0..16256)
    const int o0 = blockIdx.y * 128;        // out-channel tile base (0 or 128)
    const int z  = blockIdx.z;              // 0..23
    const int ii = z >> 1;                  // tensor index 0..11
    const int bb = z & 1;                   // batch

    const float* Xg = xs.p[ii] + (size_t)bb * (C_IN * PIX);

    const int warp_m = (warp >> 2) * 64;    // out-channel offset within tile
    const int warp_n = (warp & 3) * 32;     // pixel offset within tile

    float d[4][4][4];
    #pragma unroll
    for (int mb = 0; mb < 4; ++mb)
        #pragma unroll
        for (int nb = 0; nb < 4; ++nb)
            #pragma unroll
            for (int r = 0; r < 4; ++r)
                d[mb][nb][r] = 0.0f;

    // ---- async stage loader: W tile [KB][128] and X tile [KB][128], padded rows ----
    auto load_stage = [&](int kc, int s) {
        float* Wst = smem + s * (2 * STAGE_F);
        float* Xst = Wst + STAGE_F;
        #pragma unroll
        for (int it = 0; it < 4; ++it) {
            int idx = it * 256 + tid;       // 0..1023 float4 slots
            int row = idx >> 5;             // 0..31 (k within chunk)
            int col = (idx & 31) << 2;      // 0..124
            cp16_ca(Wst + row * ROWPAD + col, Wg + (size_t)(kc + row) * C_OUT + o0 + col);
            cp16_cg(Xst + row * ROWPAD + col, Xg + (size_t)(kc + row) * PIX + p0 + col);
        }
        asm volatile("cp.async.commit_group;");
    };

    load_stage(0, 0);

    #pragma unroll 1
    for (int kc = 0; kc < C_IN; kc += KB) {
        asm volatile("cp.async.wait_group 0;");
        __syncthreads();   // stage (kc) ready; all threads done reading the other buffer

        const int s = (kc / KB) & 1;
        if (kc + KB < C_IN) load_stage(kc + KB, s ^ 1);

        const float* Wst = smem + s * (2 * STAGE_F);
        const float* Xst = Wst + STAGE_F;

        #pragma unroll
        for (int ks = 0; ks < KB; ks += 8) {
            const int kr = ks + tig;

            // A fragments: A[m=o][k=c] = Wst[c][o]
            uint32_t a[4][4];
            #pragma unroll
            for (int mb = 0; mb < 4; ++mb) {
                const int m = warp_m + mb * 16 + gid;
                a[mb][0] = f2tf32(Wst[(kr)     * ROWPAD + m]);
                a[mb][1] = f2tf32(Wst[(kr)     * ROWPAD + m + 8]);
                a[mb][2] = f2tf32(Wst[(kr + 4) * ROWPAD + m]);
                a[mb][3] = f2tf32(Wst[(kr + 4) * ROWPAD + m + 8]);
            }
            // B fragments: B[k=c][n=p] = Xst[c][p]
            uint32_t bf[4][2];
            #pragma unroll
            for (int nb = 0; nb < 4; ++nb) {
                const int n = warp_n + nb * 8 + gid;
                bf[nb][0] = f2tf32(Xst[(kr)     * ROWPAD + n]);
                bf[nb][1] = f2tf32(Xst[(kr + 4) * ROWPAD + n]);
            }
            #pragma unroll
            for (int mb = 0; mb < 4; ++mb)
                #pragma unroll
                for (int nb = 0; nb < 4; ++nb)
                    mma_tf32(d[mb][nb][0], d[mb][nb][1], d[mb][nb][2], d[mb][nb][3],
                             a[mb][0], a[mb][1], a[mb][2], a[mb][3],
                             bf[nb][0], bf[nb][1]);
        }
    }

    // ---- epilogue: interleaved scatter + bias*count ----
    // c0:(row gid, col 2*tig) c1:(col+1) c2/c3:(row+8)
    #pragma unroll
    for (int mb = 0; mb < 4; ++mb) {
        const int o = o0 + warp_m + mb * 16 + gid;
        const float bv0 = bg[o];
        const float bv1 = bg[o + 8];
        #pragma unroll
        for (int nb = 0; nb < 4; ++nb) {
            const int p = p0 + warp_n + nb * 8 + 2 * tig;
            const int h = p >> 8;
            const int w = p & 255;
            const int r = 12 * h + ii;
            const int cnt = min(11, r) - max(0, r - (HOUT - 12)) + 1;
            const float fc = (float)cnt;
            const float bias0 = bv0 * fc;
            const float bias1 = bv1 * fc;
            const size_t base = ((size_t)(bb * C_OUT + o) * HOUT + r) * Ww + w;
            float2 v0 = make_float2(d[mb][nb][0] + bias0, d[mb][nb][1] + bias0);
            float2 v1 = make_float2(d[mb][nb][2] + bias1, d[mb][nb][3] + bias1);
            *reinterpret_cast<float2*>(out + base) = v0;
            *reinterpret_cast<float2*>(out + base + (size_t)8 * HOUT * Ww) = v1;
        }
    }
}

extern "C" void kernel_launch(void* const* d_in, const int* in_sizes, int n_in,
                              void* d_out, int out_size)
{
    (void)in_sizes; (void)n_in; (void)out_size;

    XPtrs xs;
    for (int i = 0; i < 12; ++i) xs.p[i] = (const float*)d_in[i];
    const float* W = (const float*)d_in[12];
    const float* b = (const float*)d_in[13];
    float* out = (float*)d_out;

    cudaFuncSetAttribute(conv_interleave_kernel,
                         cudaFuncAttributeMaxDynamicSharedMemorySize, SMEM_BYTES);

    dim3 grid(PIX / 128, C_OUT / 128, 24);  // 128 x 2 x 24
    dim3 block(256);
    conv_interleave_kernel<<<grid, block, SMEM_BYTES>>>(xs, W, b, out);
}

// round 3
// speedup vs baseline: 1.1134x; 1.1134x over previous
#include <cuda_runtime.h>
#include <cstdint>

// Problem constants
#define C_IN   256
#define C_OUT  256
#define Hh     64
#define Ww     256
#define PIX    (Hh*Ww)          // 16384 pixels per (i,b)
#define HOUT   (12*Hh)          // 768

// Tiling: CTA tile = 256 (out-ch, full) x 128 (pixels), K chunks of 32.
// 8 warps, each 64x64. 3-stage cp.async pipeline.
#define KB      32
#define RPW     264             // 256+8: row stride for W tile; 264 % 32 == 8 -> conflict-free frags
#define RPX     136             // 128+8: row stride for X tile; 136 % 32 == 8
#define WST_F   (KB*RPW)        // 8448 floats
#define XST_F   (KB*RPX)        // 4352 floats
#define STAGE_F (WST_F + XST_F) // 12800 floats = 51200 B
#define NSTAGE  3
#define SMEM_BYTES (NSTAGE * STAGE_F * 4)   // 153600 B

struct XPtrs { const float* p[12]; };

__device__ __forceinline__ uint32_t f2tf32(float v) {
    uint32_t r;
    asm("cvt.rna.tf32.f32 %0, %1;" : "=r"(r) : "f"(v));
    return r;
}

__device__ __forceinline__ void mma_tf32(float& d0, float& d1, float& d2, float& d3,
                                         uint32_t a0, uint32_t a1, uint32_t a2, uint32_t a3,
                                         uint32_t b0, uint32_t b1) {
    asm volatile(
        "mma.sync.aligned.m16n8k8.row.col.f32.tf32.tf32.f32 "
        "{%0,%1,%2,%3},{%4,%5,%6,%7},{%8,%9},{%0,%1,%2,%3};"
        : "+f"(d0), "+f"(d1), "+f"(d2), "+f"(d3)
        : "r"(a0), "r"(a1), "r"(a2), "r"(a3), "r"(b0), "r"(b1));
}

__device__ __forceinline__ void cp16_cg(float* s, const float* g) {
    uint32_t sa = (uint32_t)__cvta_generic_to_shared(s);
    asm volatile("cp.async.cg.shared.global [%0], [%1], 16;\n" :: "r"(sa), "l"(g));
}
__device__ __forceinline__ void cp16_ca(float* s, const float* g) {
    uint32_t sa = (uint32_t)__cvta_generic_to_shared(s);
    asm volatile("cp.async.ca.shared.global [%0], [%1], 16;\n" :: "r"(sa), "l"(g));
}

// D[o,p] = sum_c W[c,o] * X[c,p]; out[bb, o, 12h+i, w] = D + b[o]*count(12h+i)
__global__ void __launch_bounds__(256, 1)
conv_interleave_kernel(XPtrs xs, const float* __restrict__ Wg,
                       const float* __restrict__ bg, float* __restrict__ out)
{
    extern __shared__ float smem[];

    const int tid  = threadIdx.x;
    const int lane = tid & 31;
    const int warp = tid >> 5;
    const int gid  = lane >> 2;   // groupID
    const int tig  = lane & 3;    // thread-in-group

    const int p0 = blockIdx.x * 128;        // pixel tile base
    const int z  = blockIdx.y;              // 0..23
    const int ii = z >> 1;                  // tensor index 0..11
    const int bb = z & 1;                   // batch

    const float* Xg = xs.p[ii] + (size_t)bb * (C_IN * PIX);

    const int warp_m = (warp >> 1) * 64;    // out-channel offset (0..192)
    const int warp_n = (warp & 1) * 64;     // pixel offset (0 or 64)

    float d[4][8][4];
    #pragma unroll
    for (int mb = 0; mb < 4; ++mb)
        #pragma unroll
        for (int nb = 0; nb < 8; ++nb)
            #pragma unroll
            for (int r = 0; r < 4; ++r)
                d[mb][nb][r] = 0.0f;

    // ---- async stage loader: W tile [KB][256], X tile [KB][128] ----
    auto load_stage = [&](int kc, int s) {
        float* Wst = smem + s * STAGE_F;
        float* Xst = Wst + WST_F;
        #pragma unroll
        for (int it = 0; it < 8; ++it) {        // 2048 float4 of W
            int idx = it * 256 + tid;
            int row = idx >> 6;                 // 64 float4 per row
            int col = (idx & 63) << 2;
            cp16_ca(Wst + row * RPW + col, Wg + (size_t)(kc + row) * C_OUT + col);
        }
        #pragma unroll
        for (int it = 0; it < 4; ++it) {        // 1024 float4 of X
            int idx = it * 256 + tid;
            int row = idx >> 5;                 // 32 float4 per row
            int col = (idx & 31) << 2;
            cp16_cg(Xst + row * RPX + col, Xg + (size_t)(kc + row) * PIX + p0 + col);
        }
        asm volatile("cp.async.commit_group;");
    };

    load_stage(0, 0);
    load_stage(KB, 1);

    #pragma unroll 1
    for (int kc = 0; kc < C_IN; kc += KB) {
        asm volatile("cp.async.wait_group 1;");   // stage kc complete
        __syncthreads();

        const int s = (kc / KB) % NSTAGE;
        if (kc + 2 * KB < C_IN) load_stage(kc + 2 * KB, (s + 2) % NSTAGE);

        const float* Wst = smem + s * STAGE_F;
        const float* Xst = Wst + WST_F;

        #pragma unroll
        for (int ks = 0; ks < KB; ks += 8) {
            const int kr = ks + tig;

            // A fragments: A[m=o][k=c] = Wst[c][o]
            uint32_t a[4][4];
            #pragma unroll
            for (int mb = 0; mb < 4; ++mb) {
                const int m = warp_m + mb * 16 + gid;
                a[mb][0] = f2tf32(Wst[(kr)     * RPW + m]);
                a[mb][1] = f2tf32(Wst[(kr)     * RPW + m + 8]);
                a[mb][2] = f2tf32(Wst[(kr + 4) * RPW + m]);
                a[mb][3] = f2tf32(Wst[(kr + 4) * RPW + m + 8]);
            }
            // B fragments: B[k=c][n=p] = Xst[c][p]
            uint32_t bf[8][2];
            #pragma unroll
            for (int nb = 0; nb < 8; ++nb) {
                const int n = warp_n + nb * 8 + gid;
                bf[nb][0] = f2tf32(Xst[(kr)     * RPX + n]);
                bf[nb][1] = f2tf32(Xst[(kr + 4) * RPX + n]);
            }
            #pragma unroll
            for (int mb = 0; mb < 4; ++mb)
                #pragma unroll
                for (int nb = 0; nb < 8; ++nb)
                    mma_tf32(d[mb][nb][0], d[mb][nb][1], d[mb][nb][2], d[mb][nb][3],
                             a[mb][0], a[mb][1], a[mb][2], a[mb][3],
                             bf[nb][0], bf[nb][1]);
        }
        __syncthreads();   // all warps done reading stage s before it is overwritten
    }

    // ---- epilogue: interleaved scatter + bias*count ----
    #pragma unroll
    for (int mb = 0; mb < 4; ++mb) {
        const int o = warp_m + mb * 16 + gid;
        const float bv0 = bg[o];
        const float bv1 = bg[o + 8];
        #pragma unroll
        for (int nb = 0; nb < 8; ++nb) {
            const int p = p0 + warp_n + nb * 8 + 2 * tig;
            const int h = p >> 8;
            const int w = p & 255;
            const int r = 12 * h + ii;
            const int cnt = min(11, r) - max(0, r - (HOUT - 12)) + 1;
            const float fc = (float)cnt;
            const float bias0 = bv0 * fc;
            const float bias1 = bv1 * fc;
            const size_t base = ((size_t)(bb * C_OUT + o) * HOUT + r) * Ww + w;
            float2 v0 = make_float2(d[mb][nb][0] + bias0, d[mb][nb][1] + bias0);
            float2 v1 = make_float2(d[mb][nb][2] + bias1, d[mb][nb][3] + bias1);
            *reinterpret_cast<float2*>(out + base) = v0;
            *reinterpret_cast<float2*>(out + base + (size_t)8 * HOUT * Ww) = v1;
        }
    }
}

extern "C" void kernel_launch(void* const* d_in, const int* in_sizes, int n_in,
                              void* d_out, int out_size)
{
    (void)in_sizes; (void)n_in; (void)out_size;

    XPtrs xs;
    for (int i = 0; i < 12; ++i) xs.p[i] = (const float*)d_in[i];
    const float* W = (const float*)d_in[12];
    const float* b = (const float*)d_in[13];
    float* out = (float*)d_out;

    cudaFuncSetAttribute(conv_interleave_kernel,
                         cudaFuncAttributeMaxDynamicSharedMemorySize, SMEM_BYTES);

    dim3 grid(PIX / 128, 24, 1);   // 128 pixel tiles x 24 (tensor,batch)
    dim3 block(256);
    conv_interleave_kernel<<<grid, block, SMEM_BYTES>>>(xs, W, b, out);
}